// round 14
// baseline (speedup 1.0000x reference)
#include <cuda_runtime.h>
#include <cuda_bf16.h>
#include <cstdint>

// ---------------------------------------------------------------------------
// Problem constants
// ---------------------------------------------------------------------------
#define B_    32
#define N_    512
#define OBJ   2048
#define QD    1024
#define CD    3072
#define MTOT  16384
#define STOT  ((size_t)B_ * N_ * N_)

// persistent fused-GEMM geometry: 1024 + 1024 + 320 tiles = 2368 = 296 * 8
#define NWORK   296
#define NSWEEP  8

// ---------------------------------------------------------------------------
// Device scratch (static; no runtime allocation)
// ---------------------------------------------------------------------------
__device__ __align__(16) __nv_bfloat16 g_W1hi[(size_t)QD * OBJ];
__device__ __align__(16) __nv_bfloat16 g_W2hi[(size_t)QD * QD];
__device__ __align__(16) __nv_bfloat16 g_nhi [(size_t)MTOT * OBJ];
__device__ __align__(16) __nv_bfloat16 g_h1hi[(size_t)MTOT * QD];
__device__ __align__(16) __nv_bfloat16 g_h2hi[(size_t)MTOT * QD];
__device__ __align__(16) float g_S[STOT];
__device__ __align__(16) float g_qterm[B_ * QD];
__device__ unsigned int g_odd_or = 0u;
__device__ int g_done1[128];     // per M-block GEMM1 completion (8 tiles each)
__device__ int g_done2[32];      // per batch GEMM2 completion (32 tiles each)

// upper-triangle 128x128 tile map for the symmetric GEMM3 (4x4 tile grid)
__constant__ int c_TI[10] = {0,0,0,0,1,1,1,2,2,3};
__constant__ int c_TJ[10] = {0,1,2,3,1,2,3,2,3,3};

// block-role boundaries inside prep_kernel
#define NB_CVT   32768
#define NB_WN    2048
#define NB_QT    1024
#define NB_DET   128
#define NB_TOTAL (NB_CVT + NB_WN + NB_QT + NB_DET)

// ---------------------------------------------------------------------------
// helpers
// ---------------------------------------------------------------------------
__device__ __forceinline__ uint32_t smem_u32(const void* p) {
    uint32_t a;
    asm("{ .reg .u64 t; cvta.to.shared.u64 t, %1; cvt.u32.u64 %0, t; }" : "=r"(a) : "l"(p));
    return a;
}
__device__ __forceinline__ void cp16(uint32_t dst, const void* src) {
    asm volatile("cp.async.ca.shared.global [%0], [%1], 16;" :: "r"(dst), "l"(src) : "memory");
}
__device__ __forceinline__ void cp_commit() {
    asm volatile("cp.async.commit_group;" ::: "memory");
}
template <int N>
__device__ __forceinline__ void cp_wait() {
    asm volatile("cp.async.wait_group %0;" :: "n"(N) : "memory");
}
__device__ __forceinline__ void ldsm4(uint32_t* r, uint32_t addr) {
    asm volatile("ldmatrix.sync.aligned.m8n8.x4.shared.b16 {%0,%1,%2,%3}, [%4];"
                 : "=r"(r[0]), "=r"(r[1]), "=r"(r[2]), "=r"(r[3]) : "r"(addr));
}
__device__ __forceinline__ void mma_bf16(float* c, const uint32_t* a, const uint32_t* b) {
    asm volatile(
        "mma.sync.aligned.m16n8k16.row.col.f32.bf16.bf16.f32 "
        "{%0,%1,%2,%3}, {%4,%5,%6,%7}, {%8,%9}, {%0,%1,%2,%3};"
        : "+f"(c[0]), "+f"(c[1]), "+f"(c[2]), "+f"(c[3])
        : "r"(a[0]), "r"(a[1]), "r"(a[2]), "r"(a[3]), "r"(b[0]), "r"(b[1]));
}
__device__ __forceinline__ uint32_t packbf(float lo_elem, float hi_elem) {
    uint32_t w;
    asm("cvt.rn.bf16x2.f32 %0, %1, %2;" : "=r"(w) : "f"(hi_elem), "f"(lo_elem));
    return w;
}

// ---------------------------------------------------------------------------
// Fused prep kernel (roles concurrent; also zeroes the dependency counters)
// ---------------------------------------------------------------------------
__global__ void prep_kernel(const float* __restrict__ node,
                            const float* __restrict__ qf,
                            const float* __restrict__ b1,
                            const float* __restrict__ v1,
                            const float* __restrict__ g1,
                            const float* __restrict__ v2,
                            const float* __restrict__ g2,
                            const unsigned int* __restrict__ idxw,
                            int n_words) {
    __shared__ float red[32];
    __shared__ __align__(16) float wsh[QD];

    const int bx  = blockIdx.x;
    const int tid = threadIdx.x;

    if (bx < NB_CVT) {
        size_t i4 = (size_t)bx * 256 + tid;
        float4 v = *(const float4*)(node + i4 * 4);
        uint2 hw;
        hw.x = packbf(v.x, v.y);
        hw.y = packbf(v.z, v.w);
        *(uint2*)(g_nhi + i4 * 4) = hw;
        return;
    }

    if (bx < NB_CVT + NB_WN) {
        int r = bx - NB_CVT;
        const float* src;
        int len;
        float g;
        if (r < QD) { src = v1 + (size_t)r * CD; len = CD; g = g1[r]; }
        else        { src = v2 + (size_t)(r - QD) * QD; len = QD; g = g2[r - QD]; }

        float s = 0.f;
        for (int i = tid; i < len; i += 256) { float x = src[i]; s += x * x; }
        for (int o = 16; o; o >>= 1) s += __shfl_down_sync(0xFFFFFFFFu, s, o);
        if ((tid & 31) == 0) red[tid >> 5] = s;
        __syncthreads();
        if (tid < 32) {
            float t = (tid < 8) ? red[tid] : 0.f;
            for (int o = 16; o; o >>= 1) t += __shfl_down_sync(0xFFFFFFFFu, t, o);
            if (tid == 0) red[0] = rsqrtf(t);
        }
        __syncthreads();
        float scale = g * red[0];

        if (r < QD) {
            for (int i = tid; i < OBJ; i += 256)
                g_W1hi[(size_t)r * OBJ + i] = __float2bfloat16(src[i] * scale);
        } else {
            int rr = r - QD;
            for (int i = tid; i < QD; i += 256)
                g_W2hi[(size_t)rr * QD + i] = __float2bfloat16(src[i] * scale);
        }
        return;
    }

    if (bx < NB_CVT + NB_WN + NB_QT) {
        int d = bx - (NB_CVT + NB_WN);
        const float* src = v1 + (size_t)d * CD;

        float s = 0.f;
        for (int i = tid; i < CD; i += 256) { float x = src[i]; s += x * x; }
        for (int o = 16; o; o >>= 1) s += __shfl_down_sync(0xFFFFFFFFu, s, o);
        if ((tid & 31) == 0) red[tid >> 5] = s;
        __syncthreads();
        if (tid < 32) {
            float t = (tid < 8) ? red[tid] : 0.f;
            for (int o = 16; o; o >>= 1) t += __shfl_down_sync(0xFFFFFFFFu, t, o);
            if (tid == 0) red[0] = rsqrtf(t);
        }
        __syncthreads();
        float scale = g1[d] * red[0];

        for (int i = tid; i < QD; i += 256) wsh[i] = src[OBJ + i] * scale;
        __syncthreads();

        int wid = tid >> 5, lane = tid & 31;
        float bias = b1[d];
        for (int b = wid; b < B_; b += 8) {
            const float* q = qf + (size_t)b * QD;
            float acc = 0.f;
            for (int c = lane; c < QD; c += 32) acc = fmaf(wsh[c], q[c], acc);
            for (int o = 16; o; o >>= 1) acc += __shfl_down_sync(0xFFFFFFFFu, acc, o);
            if (lane == 0) g_qterm[(size_t)b * QD + d] = acc + bias;
        }
        return;
    }

    // detect role; block 0 also zeroes the dependency counters
    {
        int db = bx - (NB_CVT + NB_WN + NB_QT);
        if (db == 0 && tid < 160) {
            if (tid < 128) g_done1[tid] = 0;
            else           g_done2[tid - 128] = 0;
        }
        int i = db * 256 + tid;
        unsigned int v = 0u;
        for (int p = 2 * i + 1; p < n_words; p += 2 * NB_DET * 256) v |= idxw[p];
        for (int o = 16; o; o >>= 1) v |= __shfl_down_sync(0xFFFFFFFFu, v, o);
        if ((tid & 31) == 0 && v) atomicOr(&g_odd_or, v);
    }
}

// ---------------------------------------------------------------------------
// Persistent fused GEMM: 296 workers x 8 tiles, ids ordered G1 | G2 | G3.
// id [0,1024):    GEMM1 tile (m=id>>3, n=id&7): h1 = relu(node@W1a^T + qterm)
// id [1024,2048): GEMM2 tile: h2 = relu(h1@W2^T + b2); gated on done1[m]==8
// id [2048,2368): GEMM3 tile (z = t/10, upper-tri): S[z] block; gated on
//                 done2[z]==32; diagonal tiles alias B smem onto A.
// GEMM core = R12-proven: 128x128 CTA tile, 8 warps (2Mx4N), warp 64x32,
// BK=32, 3-stage cp.async, SROW=40, 60 KB smem, 2 CTAs/SM, <=128 regs.
// ---------------------------------------------------------------------------
#define SROW      40
#define OFF_A     0
#define OFF_B     (128 * SROW)
#define SSTAGE    (OFF_B + 128 * SROW)       // 10240 elems = 20480 B
#define NSTAGE    3
#define GEMM_SMEM (NSTAGE * SSTAGE * 2)      // 61440 B

__global__ void __launch_bounds__(256, 2) fused_gemm(const float* __restrict__ b2) {
    extern __shared__ __align__(16) __nv_bfloat16 dsm[];
    const uint32_t sb = smem_u32(dsm);

    const int tid  = threadIdx.x;
    const int wid  = tid >> 5;
    const int lane = tid & 31;
    const int wm   = wid >> 2;
    const int wn   = wid & 3;
    const int gr   = lane >> 2;
    const int ct   = lane & 3;
    const int lg   = lane >> 3, lr = lane & 7;
    const int lrow = tid >> 1;
    const int lq   = (tid & 1) * 16;

    const uint32_t dA  = (uint32_t)((OFF_A + lrow * SROW + lq) * 2);
    const uint32_t dBb = (uint32_t)((OFF_B + lrow * SROW + lq) * 2);

    uint32_t aoffb[4], boffb[2];
#pragma unroll
    for (int mt = 0; mt < 4; mt++) {
        int row = wm * 64 + mt * 16 + (lg & 1) * 8 + lr;
        int q   = lg >> 1;
        aoffb[mt] = (uint32_t)((OFF_A + row * SROW + q * 8) * 2);
    }
#pragma unroll
    for (int p = 0; p < 2; p++) {
        int row = wn * 32 + (2 * p + (lg >> 1)) * 8 + lr;
        int q   = lg & 1;
        boffb[p] = (uint32_t)((OFF_B + row * SROW + q * 8) * 2);
    }

    for (int j = 0; j < NSWEEP; ++j) {
        const int id = blockIdx.x + NWORK * j;

        int mode, m0, n0, K, ldk, zidx = 0;
        const __nv_bfloat16 *A, *Bm;
        if (id < 1024) {
            mode = 1; m0 = (id >> 3) * 128; n0 = (id & 7) * 128;
            A = g_nhi; Bm = g_W1hi; ldk = OBJ; K = OBJ;
        } else if (id < 2048) {
            int t = id - 1024;
            mode = 2; m0 = (t >> 3) * 128; n0 = (t & 7) * 128;
            A = g_h1hi; Bm = g_W2hi; ldk = QD; K = QD;
        } else {
            int t = id - 2048;
            zidx = t / 10;
            int u = t - zidx * 10;
            mode = 0; m0 = c_TI[u] * 128; n0 = c_TJ[u] * 128;
            A = g_h2hi + (size_t)zidx * ((size_t)N_ * QD); Bm = A;
            ldk = QD; K = QD;
        }
        const bool diag = (mode == 0) && (m0 == n0);
        const uint32_t bsub = diag ? (uint32_t)((OFF_B - OFF_A) * 2) : 0u;

        // dependency gate (spin on L2 counter; producers fenced before inc)
        if (mode == 2) {
            if (tid == 0) while (atomicAdd(&g_done1[m0 >> 7], 0) < 8) {}
        } else if (mode == 0) {
            if (tid == 0) while (atomicAdd(&g_done2[zidx], 0) < 32) {}
        }
        __syncthreads();

        const __nv_bfloat16* gA = A  + (size_t)(m0 + lrow) * ldk + lq;
        const __nv_bfloat16* gB = Bm + (size_t)(n0 + lrow) * ldk + lq;

        auto issue = [&](int it) {
            const uint32_t s0 = sb + (uint32_t)((it % NSTAGE) * SSTAGE * 2);
            const size_t k0 = (size_t)it * 32;
            cp16(s0 + dA,       gA + k0);
            cp16(s0 + dA + 16,  gA + k0 + 8);
            if (!diag) {
                cp16(s0 + dBb,      gB + k0);
                cp16(s0 + dBb + 16, gB + k0 + 8);
            }
        };

        float acc[4][4][4];
#pragma unroll
        for (int i = 0; i < 4; i++)
#pragma unroll
            for (int jj = 0; jj < 4; jj++)
#pragma unroll
                for (int r = 0; r < 4; r++) acc[i][jj][r] = 0.f;

        issue(0); cp_commit();
        issue(1); cp_commit();

        const int NIT = K / 32;
        for (int it = 0; it < NIT; ++it) {
            cp_wait<1>();
            __syncthreads();
            if (it + 2 < NIT) issue(it + 2);
            cp_commit();

            const uint32_t base = sb + (uint32_t)((it % NSTAGE) * SSTAGE * 2);
#pragma unroll
            for (int ks = 0; ks < 2; ks++) {
                const uint32_t kb = base + ks * 32;
                uint32_t ah[4][4], bt[2][4];
#pragma unroll
                for (int mt = 0; mt < 4; mt++) ldsm4(ah[mt], kb + aoffb[mt]);
#pragma unroll
                for (int p = 0; p < 2; p++)    ldsm4(bt[p], kb + boffb[p] - bsub);
#pragma unroll
                for (int p = 0; p < 2; p++)
#pragma unroll
                    for (int mt = 0; mt < 4; mt++) {
                        mma_bf16(acc[mt][2 * p],     ah[mt], bt[p]);
                        mma_bf16(acc[mt][2 * p + 1], ah[mt], bt[p] + 2);
                    }
            }
        }

        // ---- epilogue ------------------------------------------------------
#pragma unroll
        for (int mt = 0; mt < 4; mt++) {
            int row_a = m0 + wm * 64 + mt * 16 + gr;
#pragma unroll
            for (int nt = 0; nt < 4; nt++) {
                int col = n0 + wn * 32 + nt * 8 + 2 * ct;
                float v0 = acc[mt][nt][0], v1 = acc[mt][nt][1];
                float v2 = acc[mt][nt][2], v3 = acc[mt][nt][3];
                if (mode == 0) {
                    float* dst = g_S + (size_t)zidx * ((size_t)N_ * N_);
                    *(float2*)(dst + (size_t)row_a * N_ + col)       = make_float2(v0, v1);
                    *(float2*)(dst + (size_t)(row_a + 8) * N_ + col) = make_float2(v2, v3);
                } else {
                    const float* bsrc = (mode == 1) ? (g_qterm + (size_t)(row_a >> 9) * QD) : b2;
                    float b0 = bsrc[col], b1v = bsrc[col + 1];
                    v0 = fmaxf(v0 + b0, 0.f);  v1 = fmaxf(v1 + b1v, 0.f);
                    v2 = fmaxf(v2 + b0, 0.f);  v3 = fmaxf(v3 + b1v, 0.f);
                    __nv_bfloat16* dh = (mode == 1) ? g_h1hi : g_h2hi;
                    *(uint32_t*)(dh + (size_t)row_a * QD + col)       = packbf(v0, v1);
                    *(uint32_t*)(dh + (size_t)(row_a + 8) * QD + col) = packbf(v2, v3);
                }
            }
        }

        // publish completion (release: every thread fences its own stores,
        // sync, then one thread bumps the counter)
        __threadfence();
        __syncthreads();
        if (tid == 0) {
            if (mode == 1)      atomicAdd(&g_done1[m0 >> 7], 1);
            else if (mode == 2) atomicAdd(&g_done2[m0 >> 9], 1);
        }
    }
}

// ---------------------------------------------------------------------------
// Gather with symmetric canonicalization (upper-triangle S only)
// ---------------------------------------------------------------------------
__global__ void gather_kernel(const void* __restrict__ idx, float* __restrict__ out, int n) {
    int e = blockIdx.x * blockDim.x + threadIdx.x;
    if (e >= n) return;
    bool is64 = (g_odd_or == 0u);
    long long v = is64 ? ((const long long*)idx)[e] : (long long)((const int*)idx)[e];
    if (v < 0) v = 0;
    if (v >= (long long)STOT) v = (long long)STOT - 1;
    unsigned int u = (unsigned int)v;
    unsigned int b  = u >> 18;
    unsigned int rn = (u >> 9) & 511u;
    unsigned int rm = u & 511u;
    unsigned int lo = min(rn, rm), hi = max(rn, rm);
    out[e] = g_S[((size_t)b << 18) | ((size_t)lo << 9) | hi];
}

// ---------------------------------------------------------------------------
// Host entry (graph-capturable: kernel launches only)
// ---------------------------------------------------------------------------
extern "C" void kernel_launch(void* const* d_in, const int* in_sizes, int n_in,
                              void* d_out, int out_size) {
    const float* node = (const float*)d_in[0];
    const float* qf   = (const float*)d_in[1];
    const void*  idx  = d_in[2];
    const float* v1   = (const float*)d_in[3];
    const float* g1   = (const float*)d_in[4];
    const float* b1   = (const float*)d_in[5];
    const float* v2   = (const float*)d_in[6];
    const float* g2   = (const float*)d_in[7];
    const float* b2   = (const float*)d_in[8];
    float*       out  = (float*)d_out;

    (void)n_in; (void)in_sizes;

    cudaFuncSetAttribute(fused_gemm, cudaFuncAttributeMaxDynamicSharedMemorySize, GEMM_SMEM);

    // slot 0: fused prep (cvt | wn | qterm | detect | counter reset)
    prep_kernel<<<NB_TOTAL, 256>>>(node, qf, b1, v1, g1, v2, g2,
                                   (const unsigned int*)idx, out_size);

    // slot 1: persistent fused GEMM1+GEMM2+GEMM3 (2368 tiles / 296 workers)
    fused_gemm<<<NWORK, 256, GEMM_SMEM>>>(b2);

    // slot 2: gather (canonicalizing)
    gather_kernel<<<(out_size + 255) / 256, 256>>>(idx, out, out_size);
}

// round 15
// speedup vs baseline: 1.0782x; 1.0782x over previous
#include <cuda_runtime.h>
#include <cuda_bf16.h>
#include <cstdint>

// ---------------------------------------------------------------------------
// Problem constants
// ---------------------------------------------------------------------------
#define B_    32
#define N_    512
#define OBJ   2048
#define QD    1024
#define CD    3072
#define MTOT  16384
#define STOT  ((size_t)B_ * N_ * N_)

// persistent fused-GEMM geometry: 1024 + 1024 + 320 tiles = 2368 = 296 * 8
#define NWORK   296
#define NSWEEP  8

// ---------------------------------------------------------------------------
// Device scratch (static; no runtime allocation)
// ---------------------------------------------------------------------------
__device__ __align__(16) __nv_bfloat16 g_W1hi[(size_t)QD * OBJ];
__device__ __align__(16) __nv_bfloat16 g_W2hi[(size_t)QD * QD];
__device__ __align__(16) __nv_bfloat16 g_nhi [(size_t)MTOT * OBJ];
__device__ __align__(16) __nv_bfloat16 g_h1hi[(size_t)MTOT * QD];
__device__ __align__(16) __nv_bfloat16 g_h2hi[(size_t)MTOT * QD];
__device__ __align__(16) float g_S[STOT];
__device__ __align__(16) float g_qterm[B_ * QD];
__device__ unsigned int g_odd_or = 0u;
__device__ int g_done1[128];     // per M-block GEMM1 completion (8 tiles each)
__device__ int g_done2[32];      // per batch GEMM2 completion (32 tiles each)

// upper-triangle 128x128 tile map for the symmetric GEMM3 (4x4 tile grid)
__constant__ int c_TI[10] = {0,0,0,0,1,1,1,2,2,3};
__constant__ int c_TJ[10] = {0,1,2,3,1,2,3,2,3,3};

// block-role boundaries inside prep_kernel
#define NB_CVT   32768
#define NB_WN    2048
#define NB_QT    1024
#define NB_DET   128
#define NB_TOTAL (NB_CVT + NB_WN + NB_QT + NB_DET)

// ---------------------------------------------------------------------------
// helpers
// ---------------------------------------------------------------------------
__device__ __forceinline__ uint32_t smem_u32(const void* p) {
    uint32_t a;
    asm("{ .reg .u64 t; cvta.to.shared.u64 t, %1; cvt.u32.u64 %0, t; }" : "=r"(a) : "l"(p));
    return a;
}
__device__ __forceinline__ void cp16(uint32_t dst, const void* src) {
    asm volatile("cp.async.ca.shared.global [%0], [%1], 16;" :: "r"(dst), "l"(src) : "memory");
}
__device__ __forceinline__ void cp_commit() {
    asm volatile("cp.async.commit_group;" ::: "memory");
}
template <int N>
__device__ __forceinline__ void cp_wait() {
    asm volatile("cp.async.wait_group %0;" :: "n"(N) : "memory");
}
__device__ __forceinline__ void ldsm4(uint32_t* r, uint32_t addr) {
    asm volatile("ldmatrix.sync.aligned.m8n8.x4.shared.b16 {%0,%1,%2,%3}, [%4];"
                 : "=r"(r[0]), "=r"(r[1]), "=r"(r[2]), "=r"(r[3]) : "r"(addr));
}
__device__ __forceinline__ void mma_bf16(float* c, const uint32_t* a, const uint32_t* b) {
    asm volatile(
        "mma.sync.aligned.m16n8k16.row.col.f32.bf16.bf16.f32 "
        "{%0,%1,%2,%3}, {%4,%5,%6,%7}, {%8,%9}, {%0,%1,%2,%3};"
        : "+f"(c[0]), "+f"(c[1]), "+f"(c[2]), "+f"(c[3])
        : "r"(a[0]), "r"(a[1]), "r"(a[2]), "r"(a[3]), "r"(b[0]), "r"(b[1]));
}
__device__ __forceinline__ uint32_t packbf(float lo_elem, float hi_elem) {
    uint32_t w;
    asm("cvt.rn.bf16x2.f32 %0, %1, %2;" : "=r"(w) : "f"(hi_elem), "f"(lo_elem));
    return w;
}

// ---------------------------------------------------------------------------
// Fused prep kernel (roles concurrent; also zeroes the dependency counters)
// ---------------------------------------------------------------------------
__global__ void prep_kernel(const float* __restrict__ node,
                            const float* __restrict__ qf,
                            const float* __restrict__ b1,
                            const float* __restrict__ v1,
                            const float* __restrict__ g1,
                            const float* __restrict__ v2,
                            const float* __restrict__ g2,
                            const unsigned int* __restrict__ idxw,
                            int n_words) {
    __shared__ float red[32];
    __shared__ __align__(16) float wsh[QD];

    const int bx  = blockIdx.x;
    const int tid = threadIdx.x;

    if (bx < NB_CVT) {
        size_t i4 = (size_t)bx * 256 + tid;
        float4 v = *(const float4*)(node + i4 * 4);
        uint2 hw;
        hw.x = packbf(v.x, v.y);
        hw.y = packbf(v.z, v.w);
        *(uint2*)(g_nhi + i4 * 4) = hw;
        return;
    }

    if (bx < NB_CVT + NB_WN) {
        int r = bx - NB_CVT;
        const float* src;
        int len;
        float g;
        if (r < QD) { src = v1 + (size_t)r * CD; len = CD; g = g1[r]; }
        else        { src = v2 + (size_t)(r - QD) * QD; len = QD; g = g2[r - QD]; }

        float s = 0.f;
        for (int i = tid; i < len; i += 256) { float x = src[i]; s += x * x; }
        for (int o = 16; o; o >>= 1) s += __shfl_down_sync(0xFFFFFFFFu, s, o);
        if ((tid & 31) == 0) red[tid >> 5] = s;
        __syncthreads();
        if (tid < 32) {
            float t = (tid < 8) ? red[tid] : 0.f;
            for (int o = 16; o; o >>= 1) t += __shfl_down_sync(0xFFFFFFFFu, t, o);
            if (tid == 0) red[0] = rsqrtf(t);
        }
        __syncthreads();
        float scale = g * red[0];

        if (r < QD) {
            for (int i = tid; i < OBJ; i += 256)
                g_W1hi[(size_t)r * OBJ + i] = __float2bfloat16(src[i] * scale);
        } else {
            int rr = r - QD;
            for (int i = tid; i < QD; i += 256)
                g_W2hi[(size_t)rr * QD + i] = __float2bfloat16(src[i] * scale);
        }
        return;
    }

    if (bx < NB_CVT + NB_WN + NB_QT) {
        int d = bx - (NB_CVT + NB_WN);
        const float* src = v1 + (size_t)d * CD;

        float s = 0.f;
        for (int i = tid; i < CD; i += 256) { float x = src[i]; s += x * x; }
        for (int o = 16; o; o >>= 1) s += __shfl_down_sync(0xFFFFFFFFu, s, o);
        if ((tid & 31) == 0) red[tid >> 5] = s;
        __syncthreads();
        if (tid < 32) {
            float t = (tid < 8) ? red[tid] : 0.f;
            for (int o = 16; o; o >>= 1) t += __shfl_down_sync(0xFFFFFFFFu, t, o);
            if (tid == 0) red[0] = rsqrtf(t);
        }
        __syncthreads();
        float scale = g1[d] * red[0];

        for (int i = tid; i < QD; i += 256) wsh[i] = src[OBJ + i] * scale;
        __syncthreads();

        int wid = tid >> 5, lane = tid & 31;
        float bias = b1[d];
        for (int b = wid; b < B_; b += 8) {
            const float* q = qf + (size_t)b * QD;
            float acc = 0.f;
            for (int c = lane; c < QD; c += 32) acc = fmaf(wsh[c], q[c], acc);
            for (int o = 16; o; o >>= 1) acc += __shfl_down_sync(0xFFFFFFFFu, acc, o);
            if (lane == 0) g_qterm[(size_t)b * QD + d] = acc + bias;
        }
        return;
    }

    // detect role; block 0 also zeroes the dependency counters
    {
        int db = bx - (NB_CVT + NB_WN + NB_QT);
        if (db == 0 && tid < 160) {
            if (tid < 128) g_done1[tid] = 0;
            else           g_done2[tid - 128] = 0;
        }
        int i = db * 256 + tid;
        unsigned int v = 0u;
        for (int p = 2 * i + 1; p < n_words; p += 2 * NB_DET * 256) v |= idxw[p];
        for (int o = 16; o; o >>= 1) v |= __shfl_down_sync(0xFFFFFFFFu, v, o);
        if ((tid & 31) == 0 && v) atomicOr(&g_odd_or, v);
    }
}

// ---------------------------------------------------------------------------
// Templated GEMM tile body (constexpr K / ldk / NIT -> proven R12 codegen).
// MODE 1: h1 = relu(A@B^T + qterm); MODE 2: h2 = relu(A@B^T + b2);
// MODE 0: S[z] block (fp32), optional diag aliasing of B onto A smem.
// ---------------------------------------------------------------------------
#define SROW      40
#define OFF_A     0
#define OFF_B     (128 * SROW)
#define SSTAGE    (OFF_B + 128 * SROW)       // 10240 elems = 20480 B
#define NSTAGE    3
#define GEMM_SMEM (NSTAGE * SSTAGE * 2)      // 61440 B

template <int MODE>
__device__ __forceinline__ void gemm_tile(uint32_t sb, int m0, int n0, int zidx,
                                          bool diag,
                                          const __nv_bfloat16* __restrict__ A,
                                          const __nv_bfloat16* __restrict__ Bm,
                                          const float* __restrict__ bias) {
    constexpr int K   = (MODE == 1) ? OBJ : QD;
    constexpr int NIT = K / 32;
    constexpr size_t ldk = (MODE == 1) ? OBJ : QD;

    const int tid  = threadIdx.x;
    const int wid  = tid >> 5;
    const int lane = tid & 31;
    const int wm   = wid >> 2;
    const int wn   = wid & 3;
    const int gr   = lane >> 2;
    const int ct   = lane & 3;
    const int lg   = lane >> 3, lr = lane & 7;
    const int lrow = tid >> 1;
    const int lq   = (tid & 1) * 16;

    const uint32_t dA  = (uint32_t)((OFF_A + lrow * SROW + lq) * 2);
    const uint32_t dBb = (uint32_t)((OFF_B + lrow * SROW + lq) * 2);

    const __nv_bfloat16* gA = A  + (size_t)(m0 + lrow) * ldk + lq;
    const __nv_bfloat16* gB = Bm + (size_t)(n0 + lrow) * ldk + lq;

    auto issue = [&](int it) {
        const uint32_t s0 = sb + (uint32_t)((it % NSTAGE) * SSTAGE * 2);
        const size_t k0 = (size_t)it * 32;
        cp16(s0 + dA,       gA + k0);
        cp16(s0 + dA + 16,  gA + k0 + 8);
        if (!diag) {
            cp16(s0 + dBb,      gB + k0);
            cp16(s0 + dBb + 16, gB + k0 + 8);
        }
    };

    uint32_t aoffb[4], boffb[2];
#pragma unroll
    for (int mt = 0; mt < 4; mt++) {
        int row = wm * 64 + mt * 16 + (lg & 1) * 8 + lr;
        int q   = lg >> 1;
        aoffb[mt] = (uint32_t)((OFF_A + row * SROW + q * 8) * 2);
    }
    const int offB = diag ? OFF_A : OFF_B;
#pragma unroll
    for (int p = 0; p < 2; p++) {
        int row = wn * 32 + (2 * p + (lg >> 1)) * 8 + lr;
        int q   = lg & 1;
        boffb[p] = (uint32_t)((offB + row * SROW + q * 8) * 2);
    }

    float acc[4][4][4];
#pragma unroll
    for (int i = 0; i < 4; i++)
#pragma unroll
        for (int j = 0; j < 4; j++)
#pragma unroll
            for (int r = 0; r < 4; r++) acc[i][j][r] = 0.f;

    issue(0); cp_commit();
    issue(1); cp_commit();

    for (int it = 0; it < NIT; ++it) {
        cp_wait<1>();
        __syncthreads();
        if (it + 2 < NIT) issue(it + 2);
        cp_commit();

        const uint32_t base = sb + (uint32_t)((it % NSTAGE) * SSTAGE * 2);
#pragma unroll
        for (int ks = 0; ks < 2; ks++) {
            const uint32_t kb = base + ks * 32;
            uint32_t ah[4][4], bt[2][4];
#pragma unroll
            for (int mt = 0; mt < 4; mt++) ldsm4(ah[mt], kb + aoffb[mt]);
#pragma unroll
            for (int p = 0; p < 2; p++)    ldsm4(bt[p], kb + boffb[p]);
#pragma unroll
            for (int p = 0; p < 2; p++)
#pragma unroll
                for (int mt = 0; mt < 4; mt++) {
                    mma_bf16(acc[mt][2 * p],     ah[mt], bt[p]);
                    mma_bf16(acc[mt][2 * p + 1], ah[mt], bt[p] + 2);
                }
        }
    }

    // ---- epilogue -----------------------------------------------------------
#pragma unroll
    for (int mt = 0; mt < 4; mt++) {
        int row_a = m0 + wm * 64 + mt * 16 + gr;
#pragma unroll
        for (int nt = 0; nt < 4; nt++) {
            int col = n0 + wn * 32 + nt * 8 + 2 * ct;
            float v0 = acc[mt][nt][0], v1 = acc[mt][nt][1];
            float v2 = acc[mt][nt][2], v3 = acc[mt][nt][3];
            if (MODE == 0) {
                float* dst = g_S + (size_t)zidx * ((size_t)N_ * N_);
                *(float2*)(dst + (size_t)row_a * N_ + col)       = make_float2(v0, v1);
                *(float2*)(dst + (size_t)(row_a + 8) * N_ + col) = make_float2(v2, v3);
            } else {
                const float* bsrc = (MODE == 1) ? (g_qterm + (size_t)(row_a >> 9) * QD) : bias;
                float b0 = bsrc[col], b1v = bsrc[col + 1];
                v0 = fmaxf(v0 + b0, 0.f);  v1 = fmaxf(v1 + b1v, 0.f);
                v2 = fmaxf(v2 + b0, 0.f);  v3 = fmaxf(v3 + b1v, 0.f);
                __nv_bfloat16* dh = (MODE == 1) ? g_h1hi : g_h2hi;
                *(uint32_t*)(dh + (size_t)row_a * QD + col)       = packbf(v0, v1);
                *(uint32_t*)(dh + (size_t)(row_a + 8) * QD + col) = packbf(v2, v3);
            }
        }
    }
}

// ---------------------------------------------------------------------------
// Persistent fused GEMM: 296 workers x 8 tiles, ids ordered G1 | G2 | G3.
// Dependencies: G2 tile (m,.) gated on done1[m]==8; G3 batch z on done2[z]==32.
// ---------------------------------------------------------------------------
__global__ void __launch_bounds__(256, 2) fused_gemm(const float* __restrict__ b2) {
    extern __shared__ __align__(16) __nv_bfloat16 dsm[];
    const uint32_t sb = smem_u32(dsm);
    const int tid = threadIdx.x;

    for (int j = 0; j < NSWEEP; ++j) {
        const int id = blockIdx.x + NWORK * j;

        if (id < 1024) {
            const int m0 = (id >> 3) * 128, n0 = (id & 7) * 128;
            gemm_tile<1>(sb, m0, n0, 0, false, g_nhi, g_W1hi, nullptr);
            __threadfence();
            __syncthreads();
            if (tid == 0) atomicAdd(&g_done1[m0 >> 7], 1);
        } else if (id < 2048) {
            const int t = id - 1024;
            const int m0 = (t >> 3) * 128, n0 = (t & 7) * 128;
            if (tid == 0) while (atomicAdd(&g_done1[m0 >> 7], 0) < 8) {}
            __syncthreads();
            gemm_tile<2>(sb, m0, n0, 0, false, g_h1hi, g_W2hi, b2);
            __threadfence();
            __syncthreads();
            if (tid == 0) atomicAdd(&g_done2[m0 >> 9], 1);
        } else {
            const int t = id - 2048;
            const int zidx = t / 10;
            const int u = t - zidx * 10;
            const int m0 = c_TI[u] * 128, n0 = c_TJ[u] * 128;
            if (tid == 0) while (atomicAdd(&g_done2[zidx], 0) < 32) {}
            __syncthreads();
            const __nv_bfloat16* A = g_h2hi + (size_t)zidx * ((size_t)N_ * QD);
            gemm_tile<0>(sb, m0, n0, zidx, m0 == n0, A, A, nullptr);
            __syncthreads();   // smem reuse safety before next tile
        }
    }
}

// ---------------------------------------------------------------------------
// Gather with symmetric canonicalization (upper-triangle S only)
// ---------------------------------------------------------------------------
__global__ void gather_kernel(const void* __restrict__ idx, float* __restrict__ out, int n) {
    int e = blockIdx.x * blockDim.x + threadIdx.x;
    if (e >= n) return;
    bool is64 = (g_odd_or == 0u);
    long long v = is64 ? ((const long long*)idx)[e] : (long long)((const int*)idx)[e];
    if (v < 0) v = 0;
    if (v >= (long long)STOT) v = (long long)STOT - 1;
    unsigned int u = (unsigned int)v;
    unsigned int b  = u >> 18;
    unsigned int rn = (u >> 9) & 511u;
    unsigned int rm = u & 511u;
    unsigned int lo = min(rn, rm), hi = max(rn, rm);
    out[e] = g_S[((size_t)b << 18) | ((size_t)lo << 9) | hi];
}

// ---------------------------------------------------------------------------
// Host entry (graph-capturable: kernel launches only)
// ---------------------------------------------------------------------------
extern "C" void kernel_launch(void* const* d_in, const int* in_sizes, int n_in,
                              void* d_out, int out_size) {
    const float* node = (const float*)d_in[0];
    const float* qf   = (const float*)d_in[1];
    const void*  idx  = d_in[2];
    const float* v1   = (const float*)d_in[3];
    const float* g1   = (const float*)d_in[4];
    const float* b1   = (const float*)d_in[5];
    const float* v2   = (const float*)d_in[6];
    const float* g2   = (const float*)d_in[7];
    const float* b2   = (const float*)d_in[8];
    float*       out  = (float*)d_out;

    (void)n_in; (void)in_sizes;

    cudaFuncSetAttribute(fused_gemm, cudaFuncAttributeMaxDynamicSharedMemorySize, GEMM_SMEM);

    // slot 0: fused prep (cvt | wn | qterm | detect | counter reset)
    prep_kernel<<<NB_TOTAL, 256>>>(node, qf, b1, v1, g1, v2, g2,
                                   (const unsigned int*)idx, out_size);

    // slot 1: persistent fused GEMM1+GEMM2+GEMM3 (2368 tiles / 296 workers)
    fused_gemm<<<NWORK, 256, GEMM_SMEM>>>(b2);

    // slot 2: gather (canonicalizing)
    gather_kernel<<<(out_size + 255) / 256, 256>>>(idx, out, out_size);
}

// round 16
// speedup vs baseline: 1.0925x; 1.0132x over previous
#include <cuda_runtime.h>
#include <cuda_bf16.h>
#include <cstdint>

// ---------------------------------------------------------------------------
// Problem constants
// ---------------------------------------------------------------------------
#define B_    32
#define N_    512
#define OBJ   2048
#define QD    1024
#define CD    3072
#define MTOT  16384
#define STOT  ((size_t)B_ * N_ * N_)

// persistent fused-GEMM geometry: 1024 + 1024 + 320 tiles = 2368 = 296 * 8
#define NWORK   296
#define NSWEEP  8

// ---------------------------------------------------------------------------
// Device scratch (static; no runtime allocation)
// ---------------------------------------------------------------------------
__device__ __align__(16) __nv_bfloat16 g_W1hi[(size_t)QD * OBJ];
__device__ __align__(16) __nv_bfloat16 g_W2hi[(size_t)QD * QD];
__device__ __align__(16) __nv_bfloat16 g_nhi [(size_t)MTOT * OBJ];
__device__ __align__(16) __nv_bfloat16 g_h1hi[(size_t)MTOT * QD];
__device__ __align__(16) __nv_bfloat16 g_h2hi[(size_t)MTOT * QD];
__device__ __align__(16) float g_S[STOT];
__device__ __align__(16) float g_qterm[B_ * QD];
__device__ unsigned int g_odd_or = 0u;
__device__ int g_done1[128];     // per M-block GEMM1 completion (8 tiles each)
__device__ int g_done2[32];      // per batch GEMM2 completion (32 tiles each)

// upper-triangle 128x128 tile map for the symmetric GEMM3 (4x4 tile grid)
__constant__ int c_TI[10] = {0,0,0,0,1,1,1,2,2,3};
__constant__ int c_TJ[10] = {0,1,2,3,1,2,3,2,3,3};

// block-role boundaries inside prep_kernel
// cvt: 8192 blocks x 256 threads x 4 float4 = MTOT*OBJ floats
#define NB_CVT   8192
#define NB_WN    2048
#define NB_QT    1024
#define NB_DET   128
#define NB_TOTAL (NB_CVT + NB_WN + NB_QT + NB_DET)

// ---------------------------------------------------------------------------
// helpers
// ---------------------------------------------------------------------------
__device__ __forceinline__ uint32_t smem_u32(const void* p) {
    uint32_t a;
    asm("{ .reg .u64 t; cvta.to.shared.u64 t, %1; cvt.u32.u64 %0, t; }" : "=r"(a) : "l"(p));
    return a;
}
__device__ __forceinline__ void cp16(uint32_t dst, const void* src) {
    asm volatile("cp.async.ca.shared.global [%0], [%1], 16;" :: "r"(dst), "l"(src) : "memory");
}
__device__ __forceinline__ void cp_commit() {
    asm volatile("cp.async.commit_group;" ::: "memory");
}
template <int N>
__device__ __forceinline__ void cp_wait() {
    asm volatile("cp.async.wait_group %0;" :: "n"(N) : "memory");
}
__device__ __forceinline__ void ldsm4(uint32_t* r, uint32_t addr) {
    asm volatile("ldmatrix.sync.aligned.m8n8.x4.shared.b16 {%0,%1,%2,%3}, [%4];"
                 : "=r"(r[0]), "=r"(r[1]), "=r"(r[2]), "=r"(r[3]) : "r"(addr));
}
__device__ __forceinline__ void mma_bf16(float* c, const uint32_t* a, const uint32_t* b) {
    asm volatile(
        "mma.sync.aligned.m16n8k16.row.col.f32.bf16.bf16.f32 "
        "{%0,%1,%2,%3}, {%4,%5,%6,%7}, {%8,%9}, {%0,%1,%2,%3};"
        : "+f"(c[0]), "+f"(c[1]), "+f"(c[2]), "+f"(c[3])
        : "r"(a[0]), "r"(a[1]), "r"(a[2]), "r"(a[3]), "r"(b[0]), "r"(b[1]));
}
__device__ __forceinline__ uint32_t packbf(float lo_elem, float hi_elem) {
    uint32_t w;
    asm("cvt.rn.bf16x2.f32 %0, %1, %2;" : "=r"(w) : "f"(hi_elem), "f"(lo_elem));
    return w;
}

// ---------------------------------------------------------------------------
// Fused prep kernel (roles concurrent; also zeroes the dependency counters)
// cvt role: 4 independent float4 chunks per thread (MLP=4 hides DRAM latency)
// ---------------------------------------------------------------------------
__global__ void prep_kernel(const float* __restrict__ node,
                            const float* __restrict__ qf,
                            const float* __restrict__ b1,
                            const float* __restrict__ v1,
                            const float* __restrict__ g1,
                            const float* __restrict__ v2,
                            const float* __restrict__ g2,
                            const unsigned int* __restrict__ idxw,
                            int n_words) {
    __shared__ float red[32];
    __shared__ __align__(16) float wsh[QD];

    const int bx  = blockIdx.x;
    const int tid = threadIdx.x;

    if (bx < NB_CVT) {
        // ---- node_feats fp32 -> bf16, 4 chunks per thread, loads batched ----
        size_t base = (size_t)bx * 1024 + tid;     // float4 index
        float4 v[4];
#pragma unroll
        for (int k = 0; k < 4; k++)
            v[k] = *(const float4*)(node + (base + k * 256) * 4);
#pragma unroll
        for (int k = 0; k < 4; k++) {
            uint2 hw;
            hw.x = packbf(v[k].x, v[k].y);
            hw.y = packbf(v[k].z, v[k].w);
            *(uint2*)(g_nhi + (base + k * 256) * 4) = hw;
        }
        return;
    }

    if (bx < NB_CVT + NB_WN) {
        int r = bx - NB_CVT;
        const float* src;
        int len;
        float g;
        if (r < QD) { src = v1 + (size_t)r * CD; len = CD; g = g1[r]; }
        else        { src = v2 + (size_t)(r - QD) * QD; len = QD; g = g2[r - QD]; }

        float s = 0.f;
        for (int i = tid; i < len; i += 256) { float x = src[i]; s += x * x; }
        for (int o = 16; o; o >>= 1) s += __shfl_down_sync(0xFFFFFFFFu, s, o);
        if ((tid & 31) == 0) red[tid >> 5] = s;
        __syncthreads();
        if (tid < 32) {
            float t = (tid < 8) ? red[tid] : 0.f;
            for (int o = 16; o; o >>= 1) t += __shfl_down_sync(0xFFFFFFFFu, t, o);
            if (tid == 0) red[0] = rsqrtf(t);
        }
        __syncthreads();
        float scale = g * red[0];

        if (r < QD) {
            for (int i = tid; i < OBJ; i += 256)
                g_W1hi[(size_t)r * OBJ + i] = __float2bfloat16(src[i] * scale);
        } else {
            int rr = r - QD;
            for (int i = tid; i < QD; i += 256)
                g_W2hi[(size_t)rr * QD + i] = __float2bfloat16(src[i] * scale);
        }
        return;
    }

    if (bx < NB_CVT + NB_WN + NB_QT) {
        int d = bx - (NB_CVT + NB_WN);
        const float* src = v1 + (size_t)d * CD;

        float s = 0.f;
        for (int i = tid; i < CD; i += 256) { float x = src[i]; s += x * x; }
        for (int o = 16; o; o >>= 1) s += __shfl_down_sync(0xFFFFFFFFu, s, o);
        if ((tid & 31) == 0) red[tid >> 5] = s;
        __syncthreads();
        if (tid < 32) {
            float t = (tid < 8) ? red[tid] : 0.f;
            for (int o = 16; o; o >>= 1) t += __shfl_down_sync(0xFFFFFFFFu, t, o);
            if (tid == 0) red[0] = rsqrtf(t);
        }
        __syncthreads();
        float scale = g1[d] * red[0];

        for (int i = tid; i < QD; i += 256) wsh[i] = src[OBJ + i] * scale;
        __syncthreads();

        int wid = tid >> 5, lane = tid & 31;
        float bias = b1[d];
        for (int b = wid; b < B_; b += 8) {
            const float* q = qf + (size_t)b * QD;
            float acc = 0.f;
            for (int c = lane; c < QD; c += 32) acc = fmaf(wsh[c], q[c], acc);
            for (int o = 16; o; o >>= 1) acc += __shfl_down_sync(0xFFFFFFFFu, acc, o);
            if (lane == 0) g_qterm[(size_t)b * QD + d] = acc + bias;
        }
        return;
    }

    // detect role; block 0 also zeroes the dependency counters
    {
        int db = bx - (NB_CVT + NB_WN + NB_QT);
        if (db == 0 && tid < 160) {
            if (tid < 128) g_done1[tid] = 0;
            else           g_done2[tid - 128] = 0;
        }
        int i = db * 256 + tid;
        unsigned int v = 0u;
        for (int p = 2 * i + 1; p < n_words; p += 2 * NB_DET * 256) v |= idxw[p];
        for (int o = 16; o; o >>= 1) v |= __shfl_down_sync(0xFFFFFFFFu, v, o);
        if ((tid & 31) == 0 && v) atomicOr(&g_odd_or, v);
    }
}

// ---------------------------------------------------------------------------
// Templated GEMM tile body (constexpr K / ldk / NIT -> proven R12 codegen).
// MODE 1: h1 = relu(A@B^T + qterm); MODE 2: h2 = relu(A@B^T + b2);
// MODE 0: S[z] block (fp32), optional diag aliasing of B onto A smem.
// ---------------------------------------------------------------------------
#define SROW      40
#define OFF_A     0
#define OFF_B     (128 * SROW)
#define SSTAGE    (OFF_B + 128 * SROW)       // 10240 elems = 20480 B
#define NSTAGE    3
#define GEMM_SMEM (NSTAGE * SSTAGE * 2)      // 61440 B

template <int MODE>
__device__ __forceinline__ void gemm_tile(uint32_t sb, int m0, int n0, int zidx,
                                          bool diag,
                                          const __nv_bfloat16* __restrict__ A,
                                          const __nv_bfloat16* __restrict__ Bm,
                                          const float* __restrict__ bias) {
    constexpr int K   = (MODE == 1) ? OBJ : QD;
    constexpr int NIT = K / 32;
    constexpr size_t ldk = (MODE == 1) ? OBJ : QD;

    const int tid  = threadIdx.x;
    const int wid  = tid >> 5;
    const int lane = tid & 31;
    const int wm   = wid >> 2;
    const int wn   = wid & 3;
    const int gr   = lane >> 2;
    const int ct   = lane & 3;
    const int lg   = lane >> 3, lr = lane & 7;
    const int lrow = tid >> 1;
    const int lq   = (tid & 1) * 16;

    const uint32_t dA  = (uint32_t)((OFF_A + lrow * SROW + lq) * 2);
    const uint32_t dBb = (uint32_t)((OFF_B + lrow * SROW + lq) * 2);

    const __nv_bfloat16* gA = A  + (size_t)(m0 + lrow) * ldk + lq;
    const __nv_bfloat16* gB = Bm + (size_t)(n0 + lrow) * ldk + lq;

    auto issue = [&](int it) {
        const uint32_t s0 = sb + (uint32_t)((it % NSTAGE) * SSTAGE * 2);
        const size_t k0 = (size_t)it * 32;
        cp16(s0 + dA,       gA + k0);
        cp16(s0 + dA + 16,  gA + k0 + 8);
        if (!diag) {
            cp16(s0 + dBb,      gB + k0);
            cp16(s0 + dBb + 16, gB + k0 + 8);
        }
    };

    uint32_t aoffb[4], boffb[2];
#pragma unroll
    for (int mt = 0; mt < 4; mt++) {
        int row = wm * 64 + mt * 16 + (lg & 1) * 8 + lr;
        int q   = lg >> 1;
        aoffb[mt] = (uint32_t)((OFF_A + row * SROW + q * 8) * 2);
    }
    const int offB = diag ? OFF_A : OFF_B;
#pragma unroll
    for (int p = 0; p < 2; p++) {
        int row = wn * 32 + (2 * p + (lg >> 1)) * 8 + lr;
        int q   = lg & 1;
        boffb[p] = (uint32_t)((offB + row * SROW + q * 8) * 2);
    }

    float acc[4][4][4];
#pragma unroll
    for (int i = 0; i < 4; i++)
#pragma unroll
        for (int j = 0; j < 4; j++)
#pragma unroll
            for (int r = 0; r < 4; r++) acc[i][j][r] = 0.f;

    issue(0); cp_commit();
    issue(1); cp_commit();

    for (int it = 0; it < NIT; ++it) {
        cp_wait<1>();
        __syncthreads();
        if (it + 2 < NIT) issue(it + 2);
        cp_commit();

        const uint32_t base = sb + (uint32_t)((it % NSTAGE) * SSTAGE * 2);
#pragma unroll
        for (int ks = 0; ks < 2; ks++) {
            const uint32_t kb = base + ks * 32;
            uint32_t ah[4][4], bt[2][4];
#pragma unroll
            for (int mt = 0; mt < 4; mt++) ldsm4(ah[mt], kb + aoffb[mt]);
#pragma unroll
            for (int p = 0; p < 2; p++)    ldsm4(bt[p], kb + boffb[p]);
#pragma unroll
            for (int p = 0; p < 2; p++)
#pragma unroll
                for (int mt = 0; mt < 4; mt++) {
                    mma_bf16(acc[mt][2 * p],     ah[mt], bt[p]);
                    mma_bf16(acc[mt][2 * p + 1], ah[mt], bt[p] + 2);
                }
        }
    }

    // ---- epilogue -----------------------------------------------------------
#pragma unroll
    for (int mt = 0; mt < 4; mt++) {
        int row_a = m0 + wm * 64 + mt * 16 + gr;
#pragma unroll
        for (int nt = 0; nt < 4; nt++) {
            int col = n0 + wn * 32 + nt * 8 + 2 * ct;
            float v0 = acc[mt][nt][0], v1 = acc[mt][nt][1];
            float v2 = acc[mt][nt][2], v3 = acc[mt][nt][3];
            if (MODE == 0) {
                float* dst = g_S + (size_t)zidx * ((size_t)N_ * N_);
                *(float2*)(dst + (size_t)row_a * N_ + col)       = make_float2(v0, v1);
                *(float2*)(dst + (size_t)(row_a + 8) * N_ + col) = make_float2(v2, v3);
            } else {
                const float* bsrc = (MODE == 1) ? (g_qterm + (size_t)(row_a >> 9) * QD) : bias;
                float b0 = bsrc[col], b1v = bsrc[col + 1];
                v0 = fmaxf(v0 + b0, 0.f);  v1 = fmaxf(v1 + b1v, 0.f);
                v2 = fmaxf(v2 + b0, 0.f);  v3 = fmaxf(v3 + b1v, 0.f);
                __nv_bfloat16* dh = (MODE == 1) ? g_h1hi : g_h2hi;
                *(uint32_t*)(dh + (size_t)row_a * QD + col)       = packbf(v0, v1);
                *(uint32_t*)(dh + (size_t)(row_a + 8) * QD + col) = packbf(v2, v3);
            }
        }
    }
}

// ---------------------------------------------------------------------------
// Persistent fused GEMM: 296 workers x 8 tiles, ids ordered G1 | G2 | G3.
// Dependencies: G2 tile (m,.) gated on done1[m]==8; G3 batch z on done2[z]==32.
// ---------------------------------------------------------------------------
__global__ void __launch_bounds__(256, 2) fused_gemm(const float* __restrict__ b2) {
    extern __shared__ __align__(16) __nv_bfloat16 dsm[];
    const uint32_t sb = smem_u32(dsm);
    const int tid = threadIdx.x;

    for (int j = 0; j < NSWEEP; ++j) {
        const int id = blockIdx.x + NWORK * j;

        if (id < 1024) {
            const int m0 = (id >> 3) * 128, n0 = (id & 7) * 128;
            gemm_tile<1>(sb, m0, n0, 0, false, g_nhi, g_W1hi, nullptr);
            __threadfence();
            __syncthreads();
            if (tid == 0) atomicAdd(&g_done1[m0 >> 7], 1);
        } else if (id < 2048) {
            const int t = id - 1024;
            const int m0 = (t >> 3) * 128, n0 = (t & 7) * 128;
            if (tid == 0) while (atomicAdd(&g_done1[m0 >> 7], 0) < 8) {}
            __syncthreads();
            gemm_tile<2>(sb, m0, n0, 0, false, g_h1hi, g_W2hi, b2);
            __threadfence();
            __syncthreads();
            if (tid == 0) atomicAdd(&g_done2[m0 >> 9], 1);
        } else {
            const int t = id - 2048;
            const int zidx = t / 10;
            const int u = t - zidx * 10;
            const int m0 = c_TI[u] * 128, n0 = c_TJ[u] * 128;
            if (tid == 0) while (atomicAdd(&g_done2[zidx], 0) < 32) {}
            __syncthreads();
            const __nv_bfloat16* A = g_h2hi + (size_t)zidx * ((size_t)N_ * QD);
            gemm_tile<0>(sb, m0, n0, zidx, m0 == n0, A, A, nullptr);
            __syncthreads();   // smem reuse safety before next tile
        }
    }
}

// ---------------------------------------------------------------------------
// Gather with symmetric canonicalization (upper-triangle S only)
// ---------------------------------------------------------------------------
__global__ void gather_kernel(const void* __restrict__ idx, float* __restrict__ out, int n) {
    int e = blockIdx.x * blockDim.x + threadIdx.x;
    if (e >= n) return;
    bool is64 = (g_odd_or == 0u);
    long long v = is64 ? ((const long long*)idx)[e] : (long long)((const int*)idx)[e];
    if (v < 0) v = 0;
    if (v >= (long long)STOT) v = (long long)STOT - 1;
    unsigned int u = (unsigned int)v;
    unsigned int b  = u >> 18;
    unsigned int rn = (u >> 9) & 511u;
    unsigned int rm = u & 511u;
    unsigned int lo = min(rn, rm), hi = max(rn, rm);
    out[e] = g_S[((size_t)b << 18) | ((size_t)lo << 9) | hi];
}

// ---------------------------------------------------------------------------
// Host entry (graph-capturable: kernel launches only)
// ---------------------------------------------------------------------------
extern "C" void kernel_launch(void* const* d_in, const int* in_sizes, int n_in,
                              void* d_out, int out_size) {
    const float* node = (const float*)d_in[0];
    const float* qf   = (const float*)d_in[1];
    const void*  idx  = d_in[2];
    const float* v1   = (const float*)d_in[3];
    const float* g1   = (const float*)d_in[4];
    const float* b1   = (const float*)d_in[5];
    const float* v2   = (const float*)d_in[6];
    const float* g2   = (const float*)d_in[7];
    const float* b2   = (const float*)d_in[8];
    float*       out  = (float*)d_out;

    (void)n_in; (void)in_sizes;

    cudaFuncSetAttribute(fused_gemm, cudaFuncAttributeMaxDynamicSharedMemorySize, GEMM_SMEM);

    // slot 0: fused prep (cvt | wn | qterm | detect | counter reset)
    prep_kernel<<<NB_TOTAL, 256>>>(node, qf, b1, v1, g1, v2, g2,
                                   (const unsigned int*)idx, out_size);

    // slot 1: persistent fused GEMM1+GEMM2+GEMM3 (2368 tiles / 296 workers)
    fused_gemm<<<NWORK, 256, GEMM_SMEM>>>(b2);

    // slot 2: gather (canonicalizing)
    gather_kernel<<<(out_size + 255) / 256, 256>>>(idx, out, out_size);
}